// round 14
// baseline (speedup 1.0000x reference)
#include <cuda_runtime.h>
#include <cuda_bf16.h>

#define T_STEPS 131072
#define DTF       (1.0f / 262.0f)
#define DT2F      (DTF * DTF)
#define TWO_DTF   (2.0f * DTF)
#define ETA_F     1e-6f
#define TWO_ETA_F 2e-6f
#define L2E_F     1.4426950408889634f

// MUFU helpers (separate pipe from FMA: rt 8, lat 16 — idle until now)
__device__ __forceinline__ float ex2f(float x) {
    float r; asm("ex2.approx.f32 %0, %1;" : "=f"(r) : "f"(x)); return r;
}
__device__ __forceinline__ float rcpf(float x) {
    float r; asm("rcp.approx.f32 %0, %1;" : "=f"(r) : "f"(x)); return r;
}

// Packed per-step inputs: {obs, kap*softplus(theta+garch), carma0*DT, carma1*DT}
__device__ float4 g_pack[T_STEPS];

__global__ void pack_kernel(const float* __restrict__ obs,
                            const float* __restrict__ garch,
                            const float* __restrict__ carma,
                            const float* __restrict__ kappa,
                            const float* __restrict__ theta) {
    int t = blockIdx.x * blockDim.x + threadIdx.x;
    if (t < T_STEPS) {
        float kap = log1pf(expf(kappa[0]));
        float th  = log1pf(expf(theta[0] + garch[t]));
        g_pack[t] = make_float4(obs[t], kap * th,
                                carma[2 * t] * DTF, carma[2 * t + 1] * DTF);
    }
}

__global__ void __launch_bounds__(32, 1) scan_kernel(
    const float* __restrict__ w0v, const float* __restrict__ P0,
    const float* __restrict__ b0p, const float* __restrict__ b1p,
    const float* __restrict__ a1p, const float* __restrict__ kappap,
    const float* __restrict__ xip, const float* __restrict__ rhop,
    float4* __restrict__ out) {
    if (threadIdx.x != 0) return;

    float kap  = log1pf(expf(kappap[0]));
    float xi_  = log1pf(expf(xip[0]));
    float rho_ = tanhf(rhop[0]);
    float xi2  = xi_ * xi_;
    float a1   = a1p[0];
    float f1   = b0p[0] * DTF;
    float f2   = b1p[0] * DTF;
    float dd   = 1.0f - a1 * DTF;
    float ddsq = dd * dd;
    float C0DT = (0.5f * xi2 - kap) * DTF;      // (xi^2/2 - kap)*DT
    float xrDT = xi_ * rho_ * DTF;              // cross*DT = sigma * xrDT

    // Exact eta-fold constants (posterior +eta*I absorbed into next predict):
    float P11C = 3.0f * ETA_F + DT2F * ETA_F;
    float P12C = dd * DTF * ETA_F;
    float E22C = fmaf(ddsq, ETA_F, TWO_ETA_F);

    // State (p00 dead — eliminated; p11/p22 carried without posterior eta)
    float w0 = w0v[0], w1 = w0v[1], w2 = w0v[2];
    float p01 = P0[1], p02 = P0[2];
    float p11 = P0[4], p12 = P0[5], p22 = P0[8];

    // Software-pipelined input ring (prefetch depth 8)
    float4 buf[8];
#pragma unroll
    for (int i = 0; i < 8; i++) buf[i] = g_pack[i];

    for (int t = 0; t < T_STEPS; t += 8) {
#pragma unroll
        for (int j = 0; j < 8; j++) {
            float4 d = buf[j];
            int nt = t + 8 + j;
            if (nt < T_STEPS) buf[j] = g_pack[nt];

            float obs = d.x, kth = d.y, c0d = d.z, c1d = d.w;

            // Transcendentals straight from MUFU (off the FMA pipe)
            float t0 = w0 * L2E_F;
            float En = ex2f(-t0);                   // exp(-w0)
            float E  = ex2f(t0);                    // exp(w0)   = sigma^2
            float S  = ex2f(0.5f * t0);             // exp(w0/2) = sigma
            float CS = S * xrDT;

            // --- predict ---
            float term = kth * fminf(En, 1.0f);     // kth*clip(exp(-w0),0,1)
            float dw1  = fmaf(term, DTF, C0DT);
            float a    = 1.0f - term;
            float ad   = a * dd;
            float w0p  = w0 + dw1;
            float w1p  = fmaf(w2, DTF, w1) + c0d;
            float w2p  = fmaf(dd, w2, c1d);

            float sig2p = ex2f(w0p * L2E_F);        // exp(w0_pred)

            // P_pred (Psi = diag(a,1,dd) with Psi[1,2]=DT); p00 dropped.
            float p01p = a * fmaf(p02, DTF, p01);
            float p02p = fmaf(ad, p02, CS);
            float p11p = fmaf(p22, DT2F, fmaf(p12, TWO_DTF, P11C)) + p11;
            float p12p = fmaf(dd, fmaf(p22, DTF, p12), P12C);
            float p22p = fmaf(ddsq, p22, fmaf(E, DTF, E22C));

            // --- update ---
            float QE = fmaf(sig2p, DTF, TWO_ETA_F);
            float u0 = fmaf(f1, p01p, f2 * p02p);
            float u1 = fmaf(f1, p11p, f2 * p12p);
            float u2 = fmaf(f1, p12p, f2 * p22p);
            float Q  = fmaf(f1, u1, fmaf(f2, u2, QE));
            float rq = rcpf(Q);

            float xp    = fmaf(f1, w1p, f2 * w2p);
            float innov = obs - xp;
            float K0 = u0 * rq, K1 = u1 * rq, K2 = u2 * rq;

            w0 = fmaf(K0, innov, w0p);
            w1 = fmaf(K1, innov, w1p);
            w2 = fmaf(K2, innov, w2p);

            p01 = fmaf(-K0, u1, p01p);
            p02 = fmaf(-K0, u2, p02p);
            p11 = fmaf(-K1, u1, p11p);
            p12 = fmaf(-K1, u2, p12p);
            p22 = fmaf(-K2, u2, p22p);

            out[t + j] = make_float4(xp, w0, w1, w2);
        }
    }
}

extern "C" void kernel_launch(void* const* d_in, const int* in_sizes, int n_in,
                              void* d_out, int out_size) {
    const float* obs   = (const float*)d_in[0];
    const float* garch = (const float*)d_in[1];
    const float* carma = (const float*)d_in[2];
    const float* w0v   = (const float*)d_in[3];
    const float* P0    = (const float*)d_in[4];
    const float* b0    = (const float*)d_in[5];
    const float* b1    = (const float*)d_in[6];
    const float* a1    = (const float*)d_in[7];
    const float* kappa = (const float*)d_in[8];
    const float* theta = (const float*)d_in[9];
    const float* xi    = (const float*)d_in[10];
    const float* rho   = (const float*)d_in[11];
    float4* out = (float4*)d_out;

    pack_kernel<<<(T_STEPS + 255) / 256, 256>>>(obs, garch, carma, kappa, theta);
    scan_kernel<<<1, 32>>>(w0v, P0, b0, b1, a1, kappa, xi, rho, out);
}

// round 15
// speedup vs baseline: 1.8751x; 1.8751x over previous
#include <cuda_runtime.h>
#include <cuda_bf16.h>

#define T_STEPS 131072
#define DTF       (1.0f / 262.0f)
#define DT2F      (DTF * DTF)
#define TWO_DTF   (2.0f * DTF)
#define ETA_F     1e-6f
#define TWO_ETA_F 2e-6f

// Packed per-step inputs: {obs, kap*softplus(theta+garch), carma0*DT, carma1*DT}
__device__ float4 g_pack[T_STEPS];

__global__ void pack_kernel(const float* __restrict__ obs,
                            const float* __restrict__ garch,
                            const float* __restrict__ carma,
                            const float* __restrict__ kappa,
                            const float* __restrict__ theta) {
    int t = blockIdx.x * blockDim.x + threadIdx.x;
    if (t < T_STEPS) {
        float kap = log1pf(expf(kappa[0]));
        float th  = log1pf(expf(theta[0] + garch[t]));
        g_pack[t] = make_float4(obs[t], kap * th,
                                carma[2 * t] * DTF, carma[2 * t + 1] * DTF);
    }
}

__global__ void __launch_bounds__(32, 1) scan_kernel(
    const float* __restrict__ w0v, const float* __restrict__ P0,
    const float* __restrict__ b0p, const float* __restrict__ b1p,
    const float* __restrict__ a1p, const float* __restrict__ kappap,
    const float* __restrict__ xip, const float* __restrict__ rhop,
    float4* __restrict__ out) {
    if (threadIdx.x != 0) return;

    float kap  = log1pf(expf(kappap[0]));
    float xi_  = log1pf(expf(xip[0]));
    float rho_ = tanhf(rhop[0]);
    float xi2  = xi_ * xi_;
    float a1   = a1p[0];
    float f1   = b0p[0] * DTF;
    float f2   = b1p[0] * DTF;
    float dd   = 1.0f - a1 * DTF;
    float ddsq = dd * dd;
    float C0DT = (0.5f * xi2 - kap) * DTF;      // (xi^2/2 - kap)*DT
    float xrDT = xi_ * rho_ * DTF;              // cross*DT = sigma * xrDT

    // Exact eta-fold constants (posterior +eta*I absorbed into next predict):
    float P11C = 3.0f * ETA_F + DT2F * ETA_F;
    float P12C = dd * DTF * ETA_F;
    float E22C = fmaf(ddsq, ETA_F, TWO_ETA_F);

    // State (p00 dead — eliminated; p11/p22 carried without posterior eta)
    float w0 = w0v[0], w1 = w0v[1], w2 = w0v[2];
    float p01 = P0[1], p02 = P0[2];
    float p11 = P0[4], p12 = P0[5], p22 = P0[8];

    // Carried exponentials (dw1-based Taylor, kick-free; exact resync /256)
    float E  = __expf(w0);                  // exp(w0)  = sigma^2
    float En = __expf(-w0);                 // exp(-w0)
    float CS = __expf(0.5f * w0) * xrDT;    // sigma * xi * rho * DT (resync-only)
    float rq = 1.0f / fmaf(E, DTF, TWO_ETA_F);

    // Software-pipelined input ring (prefetch depth 8)
    float4 buf[8];
#pragma unroll
    for (int i = 0; i < 8; i++) buf[i] = g_pack[i];

    for (int t = 0; t < T_STEPS; t += 8) {
        if ((t & 255) == 0) {   // periodic exact resync (bounds carry drift)
            E  = __expf(w0);
            En = __expf(-w0);
            CS = __expf(0.5f * w0) * xrDT;
        }
#pragma unroll
        for (int j = 0; j < 8; j++) {
            float4 d = buf[j];
            int nt = t + 8 + j;
            if (nt < T_STEPS) buf[j] = g_pack[nt];

            float obs = d.x, kth = d.y, c0d = d.z, c1d = d.w;

            // --- predict ---
            float term = kth * fminf(En, 1.0f);     // kth*clip(exp(-w0),0,1)
            float dw1  = fmaf(term, DTF, C0DT);
            float a    = 1.0f - term;
            float w0p  = w0 + dw1;
            float w1p  = fmaf(w2, DTF, w1) + c0d;
            float w2p  = fmaf(dd, w2, c1d);

            // Shared Taylor of exp(+/-dw1): sig2p doubles as next E carry.
            float s2   = dw1 * dw1;
            float half = fmaf(s2, 0.5f, 1.0f);
            float hp   = half + dw1;                // ~exp(+dw1)
            float hm   = half - dw1;                // ~exp(-dw1)
            float sig2p = E * hp;                   // exp(w0_pred); also E_next
            En = En * hm;                           // En_next (kick ignored)
            E  = sig2p;

            // P_pred (Psi = diag(a,1,dd) with Psi[1,2]=DT); p00 dropped.
            float p01p = a * fmaf(p02, DTF, p01);
            float p02p = fmaf(a * dd, p02, CS);
            float p11p = fmaf(p22, DT2F, fmaf(p12, TWO_DTF, P11C)) + p11;
            float p12p = fmaf(dd, fmaf(p22, DTF, p12), P12C);
            float p22p = fmaf(ddsq, p22, fmaf(sig2p, DTF, E22C));

            // --- update ---
            float QE = fmaf(sig2p, DTF, TWO_ETA_F);
            float u0 = fmaf(f1, p01p, f2 * p02p);
            float u1 = fmaf(f1, p11p, f2 * p12p);
            float u2 = fmaf(f1, p12p, f2 * p22p);
            float Q  = fmaf(f1, u1, fmaf(f2, u2, QE));
            rq = rq * fmaf(-Q, rq, 2.0f);           // Newton: rq <- rq(2-Q*rq)

            float xp    = fmaf(f1, w1p, f2 * w2p);
            float innov = obs - xp;
            float K0 = u0 * rq, K1 = u1 * rq, K2 = u2 * rq;

            w0 = fmaf(K0, innov, w0p);
            w1 = fmaf(K1, innov, w1p);
            w2 = fmaf(K2, innov, w2p);

            p01 = fmaf(-K0, u1, p01p);
            p02 = fmaf(-K0, u2, p02p);
            p11 = fmaf(-K1, u1, p11p);
            p12 = fmaf(-K1, u2, p12p);
            p22 = fmaf(-K2, u2, p22p);

            out[t + j] = make_float4(xp, w0, w1, w2);
        }
    }
}

extern "C" void kernel_launch(void* const* d_in, const int* in_sizes, int n_in,
                              void* d_out, int out_size) {
    const float* obs   = (const float*)d_in[0];
    const float* garch = (const float*)d_in[1];
    const float* carma = (const float*)d_in[2];
    const float* w0v   = (const float*)d_in[3];
    const float* P0    = (const float*)d_in[4];
    const float* b0    = (const float*)d_in[5];
    const float* b1    = (const float*)d_in[6];
    const float* a1    = (const float*)d_in[7];
    const float* kappa = (const float*)d_in[8];
    const float* theta = (const float*)d_in[9];
    const float* xi    = (const float*)d_in[10];
    const float* rho   = (const float*)d_in[11];
    float4* out = (float4*)d_out;

    pack_kernel<<<(T_STEPS + 255) / 256, 256>>>(obs, garch, carma, kappa, theta);
    scan_kernel<<<1, 32>>>(w0v, P0, b0, b1, a1, kappa, xi, rho, out);
}